// round 12
// baseline (speedup 1.0000x reference)
#include <cuda_runtime.h>
#include <cuda_fp16.h>
#include <math.h>
#include <stdint.h>

// Problem shape (fixed): B=16, Lq=Lk=2048, Dq=Dk=Dv=1024
#define BATCH 16
#define LQ 2048
#define LK 2048
#define DM 1024

// GEMM tiling: CTA 128x256x32, warp 64x64, 8 warps, 4-stage cp.async pipeline
#define BM 128
#define BN 256
#define BK 32
#define NTH 256

// smem: K-major fp16 tiles, 64B data rows padded to 80B (conflict-free LDSM)
#define ROWB 80
#define A_TILE_B (128 * ROWB)            // 10240
#define B_TILE_B (256 * ROWB)            // 20480
#define STAGE_SZ (A_TILE_B + B_TILE_B)   // 30720
#define NSTAGE 4
#define DYN_SMEM (NSTAGE * STAGE_SZ)     // 122880

// ---------------- device scratch (preconverted fp16 operands) ----------------
__device__ __half g_qh[(size_t)BATCH * LQ * DM];    // Q fp16
__device__ __half g_kh[(size_t)BATCH * LK * DM];    // K fp16
__device__ __half g_wh[(size_t)DM * DM];            // W fp16
__device__ __half g_kth[(size_t)BATCH * LK * DM];   // tanh(K W^T) fp16
__device__ __half g_vth[(size_t)BATCH * DM * LK];   // V^T fp16
__device__ __half g_ath[(size_t)BATCH * LQ * LK];   // att fp16

// ---------------- helpers ----------------
__device__ __forceinline__ uint2 round4h(float4 v) {
    __half2 H01; H01.x = __float2half(v.x); H01.y = __float2half(v.y);
    __half2 H23; H23.x = __float2half(v.z); H23.y = __float2half(v.w);
    uint2 r;
    r.x = *reinterpret_cast<uint32_t*>(&H01);
    r.y = *reinterpret_cast<uint32_t*>(&H23);
    return r;
}

__device__ __forceinline__ void mma_f16(float* d, const uint32_t* a, const uint32_t* b) {
    asm volatile(
        "mma.sync.aligned.m16n8k16.row.col.f32.f16.f16.f32 "
        "{%0,%1,%2,%3},{%4,%5,%6,%7},{%8,%9},{%0,%1,%2,%3};"
        : "+f"(d[0]), "+f"(d[1]), "+f"(d[2]), "+f"(d[3])
        : "r"(a[0]), "r"(a[1]), "r"(a[2]), "r"(a[3]), "r"(b[0]), "r"(b[1]));
}

__device__ __forceinline__ void ldsm4(uint32_t* r, uint32_t a) {
    asm volatile("ldmatrix.sync.aligned.m8n8.x4.shared.b16 {%0,%1,%2,%3}, [%4];"
                 : "=r"(r[0]), "=r"(r[1]), "=r"(r[2]), "=r"(r[3]) : "r"(a));
}

__device__ __forceinline__ void cpasync16(uint32_t dst, const void* src) {
    asm volatile("cp.async.cg.shared.global [%0], [%1], 16;" :: "r"(dst), "l"(src));
}
__device__ __forceinline__ void cp_commit() {
    asm volatile("cp.async.commit_group;" ::: "memory");
}
__device__ __forceinline__ void cp_wait2() {
    asm volatile("cp.async.wait_group 2;" ::: "memory");
}

// ------------- GEMM: C[M,N] = A[M,K] * B[N,K]^T, 1-term fp16 HMMA -------------
// EPI=0: fp32 out.  EPI=1: tanh -> fp16 out.
template <int EPI>
__global__ __launch_bounds__(NTH, 1)
void gemm_h(const __half* __restrict__ Ah, const __half* __restrict__ Bh,
            float* __restrict__ Cf, __half* __restrict__ Ch,
            int M, int N, int K, long sA, long sB, long sC)
{
    constexpr uint32_t A_T = 0;
    constexpr uint32_t B_T = A_TILE_B;

    extern __shared__ char sm[];
    const uint32_t usm = (uint32_t)__cvta_generic_to_shared(sm);

    const int tid = threadIdx.x;
    const int wid = tid >> 5;
    const int lane = tid & 31;
    const int g = lane >> 2;
    const int q = lane & 3;
    const int warpM = (wid & 1) * 64;    // 0,64
    const int warpN = (wid >> 1) * 64;   // 0,64,128,192

    const int bz = blockIdx.z;
    Ah += (long)bz * sA;
    Bh += (long)bz * sB;
    if (EPI == 0) Cf += (long)bz * sC; else Ch += (long)bz * sC;

    const int rowBlk = blockIdx.y * BM;
    const int colBlk = blockIdx.x * BN;

    float acc[4][8][4];
#pragma unroll
    for (int mt = 0; mt < 4; mt++)
#pragma unroll
        for (int nt = 0; nt < 8; nt++)
#pragma unroll
            for (int j = 0; j < 4; j++) acc[mt][nt][j] = 0.0f;

    // ldmatrix lane addressing (16 rows x 16 k per ldsm4)
    const int jj = lane >> 3, lr = lane & 7;
    const uint32_t aOff = (uint32_t)((warpM + (jj & 1) * 8 + lr) * ROWB + (jj >> 1) * 16);
    const uint32_t bOff = (uint32_t)((warpN + (jj >> 1) * 8 + lr) * ROWB + (jj & 1) * 16);

    const int S = K / BK;

    // loader: 6 cp.async per thread (A 512 + B 1024 chunks of 16B)
    auto load_stage = [&](int s, uint32_t bufo) {
        const int k0 = s * BK;
#pragma unroll
        for (int i = 0; i < 2; i++) {
            const int w = tid + i * NTH;           // 0..511
            const int r = w >> 2, ch = w & 3;
            cpasync16(usm + bufo + A_T + r * ROWB + ch * 16,
                      Ah + (long)(rowBlk + r) * K + k0 + ch * 8);
        }
#pragma unroll
        for (int i = 0; i < 4; i++) {
            const int w = tid + i * NTH;           // 0..1023
            const int r = w >> 2, ch = w & 3;
            cpasync16(usm + bufo + B_T + r * ROWB + ch * 16,
                      Bh + (long)(colBlk + r) * K + k0 + ch * 8);
        }
    };

    // prologue: stages 0,1,2 (3 groups in flight)
    load_stage(0, 0);             cp_commit();
    load_stage(1, STAGE_SZ);      cp_commit();
    load_stage(2, 2 * STAGE_SZ);  cp_commit();

    for (int s = 0; s < S; s++) {
        cp_wait2();          // stage s's group completed (uniform: commit every iter)
        __syncthreads();

        if (s + 3 < S) load_stage(s + 3, (uint32_t)(((s + 3) & 3) * STAGE_SZ));
        cp_commit();         // empty group when past the end keeps wait arithmetic uniform

        const uint32_t bufo = usm + (uint32_t)((s & 3) * STAGE_SZ);
#pragma unroll
        for (int kk = 0; kk < 2; kk++) {
            const uint32_t kb = bufo + kk * 32;
            uint32_t ah[4][4];
#pragma unroll
            for (int mt = 0; mt < 4; mt++)
                ldsm4(ah[mt], kb + A_T + aOff + mt * 16 * ROWB);
            uint32_t bh[16];
#pragma unroll
            for (int i = 0; i < 4; i++)
                ldsm4(bh + i * 4, kb + B_T + bOff + i * 16 * ROWB);
#pragma unroll
            for (int nt = 0; nt < 8; nt++)
#pragma unroll
                for (int mt = 0; mt < 4; mt++)
                    mma_f16(acc[mt][nt], ah[mt], bh + nt * 2);
        }
        __syncthreads();
    }

    // ---- epilogue ----
#pragma unroll
    for (int mt = 0; mt < 4; mt++) {
        const long r0 = rowBlk + warpM + mt * 16 + g;
#pragma unroll
        for (int nt = 0; nt < 8; nt++) {
            const long c = colBlk + warpN + nt * 8 + q * 2;
            float d0 = acc[mt][nt][0], d1 = acc[mt][nt][1];
            float d2 = acc[mt][nt][2], d3 = acc[mt][nt][3];
            if (EPI == 1) {
                d0 = tanhf(d0); d1 = tanhf(d1); d2 = tanhf(d2); d3 = tanhf(d3);
                __half2 H0; H0.x = __float2half(d0); H0.y = __float2half(d1);
                __half2 H2; H2.x = __float2half(d2); H2.y = __float2half(d3);
                *reinterpret_cast<uint32_t*>(Ch + r0 * N + c)       = *reinterpret_cast<uint32_t*>(&H0);
                *reinterpret_cast<uint32_t*>(Ch + (r0 + 8) * N + c) = *reinterpret_cast<uint32_t*>(&H2);
            } else {
                float2 u; u.x = d0; u.y = d1;
                float2 w; w.x = d2; w.y = d3;
                *reinterpret_cast<float2*>(Cf + r0 * N + c) = u;
                *reinterpret_cast<float2*>(Cf + (r0 + 8) * N + c) = w;
            }
        }
    }
}

// ---------------- elementwise fp32 -> fp16 ----------------
__global__ __launch_bounds__(256) void conv_round_h(
    const float4* __restrict__ x, uint2* __restrict__ h, int n4)
{
    int i = blockIdx.x * blockDim.x + threadIdx.x;
    if (i < n4) h[i] = round4h(x[i]);
}

// ---------------- V transpose + fp16 round (vectorized 8B stores) ----------------
__global__ __launch_bounds__(256) void vtrans_kernel(
    const float* __restrict__ V, __half* __restrict__ Vh)
{
    __shared__ float t[32][33];   // t[k_local][n_local]
    const int b = blockIdx.z;
    const float* Vb = V + (long)b * LK * DM;
    const int k0 = blockIdx.x * 32, n0 = blockIdx.y * 32;
    const int tx = threadIdx.x & 31, ty = threadIdx.x >> 5;
#pragma unroll
    for (int i = 0; i < 4; i++)
        t[ty + i * 8][tx] = Vb[(long)(k0 + ty + i * 8) * DM + n0 + tx];
    __syncthreads();
    // each thread: one n, 4 consecutive k -> single 8-byte store
    const int n_l = threadIdx.x >> 3;          // 0..31
    const int k4  = (threadIdx.x & 7) * 4;     // 0,4,...,28
    float4 v4;
    v4.x = t[k4 + 0][n_l];
    v4.y = t[k4 + 1][n_l];
    v4.z = t[k4 + 2][n_l];
    v4.w = t[k4 + 3][n_l];
    uint2 hv = round4h(v4);
    const long obase = (long)b * DM * LK;
    *reinterpret_cast<uint2*>(Vh + obase + (long)(n0 + n_l) * LK + k0 + k4) = hv;
}

// ---------------- softmax: fp32 att out + fp16 att out ----------------
__global__ __launch_bounds__(256) void softmax_kernel(
    float* __restrict__ att, const int* __restrict__ kli,
    __half* __restrict__ ath)
{
    const int row = blockIdx.x;
    const int b = row >> 11;
    float* p = att + (long)row * LK;
    const int* m = kli + (long)b * LK;
    const int tid = threadIdx.x;
    const int c0 = tid * 8;
    const float scale = 0.03125f;

    float vals[8];
    {
        float4 x0 = *reinterpret_cast<const float4*>(p + c0);
        float4 x1 = *reinterpret_cast<const float4*>(p + c0 + 4);
        int4 m0 = *reinterpret_cast<const int4*>(m + c0);
        int4 m1 = *reinterpret_cast<const int4*>(m + c0 + 4);
        vals[0] = (m0.x == 0) ? -1.0e9f : x0.x * scale;
        vals[1] = (m0.y == 0) ? -1.0e9f : x0.y * scale;
        vals[2] = (m0.z == 0) ? -1.0e9f : x0.z * scale;
        vals[3] = (m0.w == 0) ? -1.0e9f : x0.w * scale;
        vals[4] = (m1.x == 0) ? -1.0e9f : x1.x * scale;
        vals[5] = (m1.y == 0) ? -1.0e9f : x1.y * scale;
        vals[6] = (m1.z == 0) ? -1.0e9f : x1.z * scale;
        vals[7] = (m1.w == 0) ? -1.0e9f : x1.w * scale;
    }

    float mx = vals[0];
#pragma unroll
    for (int i = 1; i < 8; i++) mx = fmaxf(mx, vals[i]);

    __shared__ float red[8];
#pragma unroll
    for (int o = 16; o > 0; o >>= 1)
        mx = fmaxf(mx, __shfl_xor_sync(0xffffffffu, mx, o));
    if ((tid & 31) == 0) red[tid >> 5] = mx;
    __syncthreads();
    mx = red[0];
#pragma unroll
    for (int i = 1; i < 8; i++) mx = fmaxf(mx, red[i]);
    __syncthreads();

    float sum = 0.0f;
#pragma unroll
    for (int i = 0; i < 8; i++) {
        vals[i] = expf(vals[i] - mx);
        sum += vals[i];
    }
#pragma unroll
    for (int o = 16; o > 0; o >>= 1)
        sum += __shfl_xor_sync(0xffffffffu, sum, o);
    if ((tid & 31) == 0) red[tid >> 5] = sum;
    __syncthreads();
    sum = 0.0f;
#pragma unroll
    for (int i = 0; i < 8; i++) sum += red[i];

    const float inv = 1.0f / sum;
#pragma unroll
    for (int i = 0; i < 8; i++) vals[i] *= inv;

    float4 y0; y0.x = vals[0]; y0.y = vals[1]; y0.z = vals[2]; y0.w = vals[3];
    float4 y1; y1.x = vals[4]; y1.y = vals[5]; y1.z = vals[6]; y1.w = vals[7];
    *reinterpret_cast<float4*>(p + c0) = y0;
    *reinterpret_cast<float4*>(p + c0 + 4) = y1;

    uint2 h0 = round4h(y0);
    uint2 h1 = round4h(y1);
    uint4 H; H.x = h0.x; H.y = h0.y; H.z = h1.x; H.w = h1.y;
    *reinterpret_cast<uint4*>(ath + (long)row * LK + c0) = H;
}

// ---------------- launch ----------------
extern "C" void kernel_launch(void* const* d_in, const int* in_sizes, int n_in,
                              void* d_out, int out_size)
{
    const float* q   = (const float*)d_in[0];   // [B, Lq, Dq]
    const float* k   = (const float*)d_in[1];   // [B, Lk, Dk]
    const float* v   = (const float*)d_in[2];   // [B, Lk, Dv]
    const int*   kli = (const int*)  d_in[3];   // [B, Lk]
    const float* W   = (const float*)d_in[4];   // [Dq, Dk]

    float* out = (float*)d_out;                            // [B, Lq, Dv]
    float* att = out + (size_t)BATCH * LQ * DM;            // [B, Lq, Lk]

    __half *qh, *kh, *wh, *kth, *vth, *ath;
    cudaGetSymbolAddress((void**)&qh, g_qh);
    cudaGetSymbolAddress((void**)&kh, g_kh);
    cudaGetSymbolAddress((void**)&wh, g_wh);
    cudaGetSymbolAddress((void**)&kth, g_kth);
    cudaGetSymbolAddress((void**)&vth, g_vth);
    cudaGetSymbolAddress((void**)&ath, g_ath);

    cudaFuncSetAttribute(gemm_h<0>, cudaFuncAttributeMaxDynamicSharedMemorySize, DYN_SMEM);
    cudaFuncSetAttribute(gemm_h<1>, cudaFuncAttributeMaxDynamicSharedMemorySize, DYN_SMEM);

    // 0) preconvert operands
    const int nQK4 = BATCH * LQ * DM / 4;
    conv_round_h<<<nQK4 / 256, 256>>>((const float4*)q, (uint2*)qh, nQK4);
    conv_round_h<<<nQK4 / 256, 256>>>((const float4*)k, (uint2*)kh, nQK4);
    const int nW4 = DM * DM / 4;
    conv_round_h<<<nW4 / 256, 256>>>((const float4*)W, (uint2*)wh, nW4);
    vtrans_kernel<<<dim3(LK / 32, DM / 32, BATCH), 256>>>(v, vth);

    // 1) kt = tanh(K @ W^T) -> fp16. M=Lk, N=Dq, K=Dk. W broadcast.
    gemm_h<1><<<dim3(DM / BN, LK / BM, BATCH), NTH, DYN_SMEM>>>(
        kh, wh, nullptr, kth,
        LK, DM, DM, (long)LK * DM, 0L, (long)LK * DM);

    // 2) scores = Q @ kt^T -> att (fp32). M=Lq, N=Lk, K=Dq.
    gemm_h<0><<<dim3(LK / BN, LQ / BM, BATCH), NTH, DYN_SMEM>>>(
        qh, kth, att, nullptr,
        LQ, LK, DM, (long)LQ * DM, (long)LK * DM, (long)LQ * LK);

    // 3) softmax in place + emit fp16 att
    softmax_kernel<<<BATCH * LQ, 256>>>(att, kli, ath);

    // 4) out = att @ V. M=Lq, N=Dv, K=Lk.
    gemm_h<0><<<dim3(DM / BN, LQ / BM, BATCH), NTH, DYN_SMEM>>>(
        ath, vth, out, nullptr,
        LQ, DM, LK, (long)LQ * LK, (long)DM * LK, (long)LQ * DM);
}

// round 13
// speedup vs baseline: 1.1686x; 1.1686x over previous
#include <cuda_runtime.h>
#include <cuda_fp16.h>
#include <math.h>
#include <stdint.h>

// Problem shape (fixed): B=16, Lq=Lk=2048, Dq=Dk=Dv=1024
#define BATCH 16
#define LQ 2048
#define LK 2048
#define DM 1024

// GEMM tiling: CTA 128x128x32, warp 32x64, 8 warps, 4-stage cp.async, occ 2
#define BM 128
#define BN 128
#define BK 32
#define NTH 256

// smem: K-major fp16 tiles, 64B data rows padded to 80B (conflict-free LDSM)
#define ROWB 80
#define TILE_B (128 * ROWB)          // 10240
#define STAGE_SZ (2 * TILE_B)        // 20480 (A + B)
#define NSTAGE 4
#define DYN_SMEM (NSTAGE * STAGE_SZ) // 81920 -> 2 CTAs/SM

// ---------------- device scratch (preconverted fp16 operands) ----------------
__device__ __half g_qh[(size_t)BATCH * LQ * DM];    // Q fp16
__device__ __half g_kh[(size_t)BATCH * LK * DM];    // K fp16
__device__ __half g_wh[(size_t)DM * DM];            // W fp16
__device__ __half g_kth[(size_t)BATCH * LK * DM];   // tanh(K W^T) fp16
__device__ __half g_vth[(size_t)BATCH * DM * LK];   // V^T fp16
__device__ __half g_ath[(size_t)BATCH * LQ * LK];   // att fp16

// ---------------- helpers ----------------
__device__ __forceinline__ uint2 round4h(float4 v) {
    __half2 H01; H01.x = __float2half(v.x); H01.y = __float2half(v.y);
    __half2 H23; H23.x = __float2half(v.z); H23.y = __float2half(v.w);
    uint2 r;
    r.x = *reinterpret_cast<uint32_t*>(&H01);
    r.y = *reinterpret_cast<uint32_t*>(&H23);
    return r;
}

__device__ __forceinline__ void mma_f16(float* d, const uint32_t* a, const uint32_t* b) {
    asm volatile(
        "mma.sync.aligned.m16n8k16.row.col.f32.f16.f16.f32 "
        "{%0,%1,%2,%3},{%4,%5,%6,%7},{%8,%9},{%0,%1,%2,%3};"
        : "+f"(d[0]), "+f"(d[1]), "+f"(d[2]), "+f"(d[3])
        : "r"(a[0]), "r"(a[1]), "r"(a[2]), "r"(a[3]), "r"(b[0]), "r"(b[1]));
}

__device__ __forceinline__ void ldsm4(uint32_t* r, uint32_t a) {
    asm volatile("ldmatrix.sync.aligned.m8n8.x4.shared.b16 {%0,%1,%2,%3}, [%4];"
                 : "=r"(r[0]), "=r"(r[1]), "=r"(r[2]), "=r"(r[3]) : "r"(a));
}

__device__ __forceinline__ void cpasync16(uint32_t dst, const void* src) {
    asm volatile("cp.async.cg.shared.global [%0], [%1], 16;" :: "r"(dst), "l"(src));
}
__device__ __forceinline__ void cp_commit() {
    asm volatile("cp.async.commit_group;" ::: "memory");
}
__device__ __forceinline__ void cp_wait2() {
    asm volatile("cp.async.wait_group 2;" ::: "memory");
}

// ------------- GEMM: C[M,N] = A[M,K] * B[N,K]^T, 1-term fp16 HMMA -------------
// EPI=0: fp32 out.  EPI=1: tanh -> fp16 out.
template <int EPI>
__global__ __launch_bounds__(NTH, 2)
void gemm_h(const __half* __restrict__ Ah, const __half* __restrict__ Bh,
            float* __restrict__ Cf, __half* __restrict__ Ch,
            int M, int N, int K, long sA, long sB, long sC)
{
    constexpr uint32_t A_T = 0;
    constexpr uint32_t B_T = TILE_B;

    extern __shared__ char sm[];
    const uint32_t usm = (uint32_t)__cvta_generic_to_shared(sm);

    const int tid = threadIdx.x;
    const int wid = tid >> 5;
    const int lane = tid & 31;
    const int g = lane >> 2;
    const int q = lane & 3;
    const int warpM = (wid & 3) * 32;    // 0,32,64,96
    const int warpN = (wid >> 2) * 64;   // 0,64

    const int bz = blockIdx.z;
    Ah += (long)bz * sA;
    Bh += (long)bz * sB;
    if (EPI == 0) Cf += (long)bz * sC; else Ch += (long)bz * sC;

    const int rowBlk = blockIdx.y * BM;
    const int colBlk = blockIdx.x * BN;

    float acc[2][8][4];
#pragma unroll
    for (int mt = 0; mt < 2; mt++)
#pragma unroll
        for (int nt = 0; nt < 8; nt++)
#pragma unroll
            for (int j = 0; j < 4; j++) acc[mt][nt][j] = 0.0f;

    // ldmatrix lane addressing
    const int jj = lane >> 3, lr = lane & 7;
    const uint32_t aOff = (uint32_t)((warpM + (jj & 1) * 8 + lr) * ROWB + (jj >> 1) * 16);
    const uint32_t bOff = (uint32_t)((warpN + (jj >> 1) * 8 + lr) * ROWB + (jj & 1) * 16);

    const int S = K / BK;

    // loader: 4 cp.async per thread (A 512 + B 512 chunks of 16B)
    auto load_stage = [&](int s, uint32_t bufo) {
        const int k0 = s * BK;
#pragma unroll
        for (int i = 0; i < 4; i++) {
            const int comp = i >> 1;               // 0=A, 1=B
            const int w = tid + (i & 1) * NTH;     // 0..511
            const int r = w >> 2, ch = w & 3;
            const uint32_t dst = usm + bufo + comp * TILE_B + r * ROWB + ch * 16;
            const __half* src = comp ? Bh : Ah;
            const long row = (comp ? colBlk : rowBlk) + r;
            cpasync16(dst, src + row * (long)K + k0 + ch * 8);
        }
    };

    // prologue: stages 0,1,2 (3 groups in flight)
    load_stage(0, 0);             cp_commit();
    load_stage(1, STAGE_SZ);      cp_commit();
    load_stage(2, 2 * STAGE_SZ);  cp_commit();

    for (int s = 0; s < S; s++) {
        cp_wait2();          // stage s complete (<=2 younger groups pending)
        __syncthreads();

        if (s + 3 < S) load_stage(s + 3, (uint32_t)(((s + 3) & 3) * STAGE_SZ));
        cp_commit();         // uniform commit keeps wait arithmetic exact

        const uint32_t bufo = usm + (uint32_t)((s & 3) * STAGE_SZ);
#pragma unroll
        for (int kk = 0; kk < 2; kk++) {
            const uint32_t kb = bufo + kk * 32;
            uint32_t ah[2][4];
            ldsm4(ah[0], kb + A_T + aOff);
            ldsm4(ah[1], kb + A_T + aOff + 16 * ROWB);
#pragma unroll
            for (int half = 0; half < 2; half++) {
                uint32_t bh[8];
                ldsm4(bh + 0, kb + B_T + bOff + (half * 2 + 0) * 16 * ROWB);
                ldsm4(bh + 4, kb + B_T + bOff + (half * 2 + 1) * 16 * ROWB);
#pragma unroll
                for (int n2 = 0; n2 < 4; n2++) {
                    const int nt = half * 4 + n2;
#pragma unroll
                    for (int mt = 0; mt < 2; mt++)
                        mma_f16(acc[mt][nt], ah[mt], bh + n2 * 2);
                }
            }
        }
    }

    // ---- epilogue ----
#pragma unroll
    for (int mt = 0; mt < 2; mt++) {
        const long r0 = rowBlk + warpM + mt * 16 + g;
#pragma unroll
        for (int nt = 0; nt < 8; nt++) {
            const long c = colBlk + warpN + nt * 8 + q * 2;
            float d0 = acc[mt][nt][0], d1 = acc[mt][nt][1];
            float d2 = acc[mt][nt][2], d3 = acc[mt][nt][3];
            if (EPI == 1) {
                d0 = tanhf(d0); d1 = tanhf(d1); d2 = tanhf(d2); d3 = tanhf(d3);
                __half2 H0; H0.x = __float2half(d0); H0.y = __float2half(d1);
                __half2 H2; H2.x = __float2half(d2); H2.y = __float2half(d3);
                *reinterpret_cast<uint32_t*>(Ch + r0 * N + c)       = *reinterpret_cast<uint32_t*>(&H0);
                *reinterpret_cast<uint32_t*>(Ch + (r0 + 8) * N + c) = *reinterpret_cast<uint32_t*>(&H2);
            } else {
                float2 u; u.x = d0; u.y = d1;
                float2 w; w.x = d2; w.y = d3;
                *reinterpret_cast<float2*>(Cf + r0 * N + c) = u;
                *reinterpret_cast<float2*>(Cf + (r0 + 8) * N + c) = w;
            }
        }
    }
}

// ---------------- elementwise fp32 -> fp16 ----------------
__global__ __launch_bounds__(256) void conv_round_h(
    const float4* __restrict__ x, uint2* __restrict__ h, int n4)
{
    int i = blockIdx.x * blockDim.x + threadIdx.x;
    if (i < n4) h[i] = round4h(x[i]);
}

// ---------------- V transpose + fp16 round (vectorized 8B stores) ----------------
__global__ __launch_bounds__(256) void vtrans_kernel(
    const float* __restrict__ V, __half* __restrict__ Vh)
{
    __shared__ float t[32][33];   // t[k_local][n_local]
    const int b = blockIdx.z;
    const float* Vb = V + (long)b * LK * DM;
    const int k0 = blockIdx.x * 32, n0 = blockIdx.y * 32;
    const int tx = threadIdx.x & 31, ty = threadIdx.x >> 5;
#pragma unroll
    for (int i = 0; i < 4; i++)
        t[ty + i * 8][tx] = Vb[(long)(k0 + ty + i * 8) * DM + n0 + tx];
    __syncthreads();
    // each thread: one n, 4 consecutive k -> single 8-byte store
    const int n_l = threadIdx.x >> 3;          // 0..31
    const int k4  = (threadIdx.x & 7) * 4;     // 0,4,...,28
    float4 v4;
    v4.x = t[k4 + 0][n_l];
    v4.y = t[k4 + 1][n_l];
    v4.z = t[k4 + 2][n_l];
    v4.w = t[k4 + 3][n_l];
    uint2 hv = round4h(v4);
    const long obase = (long)b * DM * LK;
    *reinterpret_cast<uint2*>(Vh + obase + (long)(n0 + n_l) * LK + k0 + k4) = hv;
}

// ---------------- softmax: fp32 att out + fp16 att out ----------------
__global__ __launch_bounds__(256) void softmax_kernel(
    float* __restrict__ att, const int* __restrict__ kli,
    __half* __restrict__ ath)
{
    const int row = blockIdx.x;
    const int b = row >> 11;
    float* p = att + (long)row * LK;
    const int* m = kli + (long)b * LK;
    const int tid = threadIdx.x;
    const int c0 = tid * 8;
    const float scale = 0.03125f;

    float vals[8];
    {
        float4 x0 = *reinterpret_cast<const float4*>(p + c0);
        float4 x1 = *reinterpret_cast<const float4*>(p + c0 + 4);
        int4 m0 = *reinterpret_cast<const int4*>(m + c0);
        int4 m1 = *reinterpret_cast<const int4*>(m + c0 + 4);
        vals[0] = (m0.x == 0) ? -1.0e9f : x0.x * scale;
        vals[1] = (m0.y == 0) ? -1.0e9f : x0.y * scale;
        vals[2] = (m0.z == 0) ? -1.0e9f : x0.z * scale;
        vals[3] = (m0.w == 0) ? -1.0e9f : x0.w * scale;
        vals[4] = (m1.x == 0) ? -1.0e9f : x1.x * scale;
        vals[5] = (m1.y == 0) ? -1.0e9f : x1.y * scale;
        vals[6] = (m1.z == 0) ? -1.0e9f : x1.z * scale;
        vals[7] = (m1.w == 0) ? -1.0e9f : x1.w * scale;
    }

    float mx = vals[0];
#pragma unroll
    for (int i = 1; i < 8; i++) mx = fmaxf(mx, vals[i]);

    __shared__ float red[8];
#pragma unroll
    for (int o = 16; o > 0; o >>= 1)
        mx = fmaxf(mx, __shfl_xor_sync(0xffffffffu, mx, o));
    if ((tid & 31) == 0) red[tid >> 5] = mx;
    __syncthreads();
    mx = red[0];
#pragma unroll
    for (int i = 1; i < 8; i++) mx = fmaxf(mx, red[i]);
    __syncthreads();

    float sum = 0.0f;
#pragma unroll
    for (int i = 0; i < 8; i++) {
        vals[i] = expf(vals[i] - mx);
        sum += vals[i];
    }
#pragma unroll
    for (int o = 16; o > 0; o >>= 1)
        sum += __shfl_xor_sync(0xffffffffu, sum, o);
    if ((tid & 31) == 0) red[tid >> 5] = sum;
    __syncthreads();
    sum = 0.0f;
#pragma unroll
    for (int i = 0; i < 8; i++) sum += red[i];

    const float inv = 1.0f / sum;
#pragma unroll
    for (int i = 0; i < 8; i++) vals[i] *= inv;

    float4 y0; y0.x = vals[0]; y0.y = vals[1]; y0.z = vals[2]; y0.w = vals[3];
    float4 y1; y1.x = vals[4]; y1.y = vals[5]; y1.z = vals[6]; y1.w = vals[7];
    *reinterpret_cast<float4*>(p + c0) = y0;
    *reinterpret_cast<float4*>(p + c0 + 4) = y1;

    uint2 h0 = round4h(y0);
    uint2 h1 = round4h(y1);
    uint4 H; H.x = h0.x; H.y = h0.y; H.z = h1.x; H.w = h1.y;
    *reinterpret_cast<uint4*>(ath + (long)row * LK + c0) = H;
}

// ---------------- launch ----------------
extern "C" void kernel_launch(void* const* d_in, const int* in_sizes, int n_in,
                              void* d_out, int out_size)
{
    const float* q   = (const float*)d_in[0];   // [B, Lq, Dq]
    const float* k   = (const float*)d_in[1];   // [B, Lk, Dk]
    const float* v   = (const float*)d_in[2];   // [B, Lk, Dv]
    const int*   kli = (const int*)  d_in[3];   // [B, Lk]
    const float* W   = (const float*)d_in[4];   // [Dq, Dk]

    float* out = (float*)d_out;                            // [B, Lq, Dv]
    float* att = out + (size_t)BATCH * LQ * DM;            // [B, Lq, Lk]

    __half *qh, *kh, *wh, *kth, *vth, *ath;
    cudaGetSymbolAddress((void**)&qh, g_qh);
    cudaGetSymbolAddress((void**)&kh, g_kh);
    cudaGetSymbolAddress((void**)&wh, g_wh);
    cudaGetSymbolAddress((void**)&kth, g_kth);
    cudaGetSymbolAddress((void**)&vth, g_vth);
    cudaGetSymbolAddress((void**)&ath, g_ath);

    cudaFuncSetAttribute(gemm_h<0>, cudaFuncAttributeMaxDynamicSharedMemorySize, DYN_SMEM);
    cudaFuncSetAttribute(gemm_h<1>, cudaFuncAttributeMaxDynamicSharedMemorySize, DYN_SMEM);

    // 0) preconvert operands
    const int nQK4 = BATCH * LQ * DM / 4;
    conv_round_h<<<nQK4 / 256, 256>>>((const float4*)q, (uint2*)qh, nQK4);
    conv_round_h<<<nQK4 / 256, 256>>>((const float4*)k, (uint2*)kh, nQK4);
    const int nW4 = DM * DM / 4;
    conv_round_h<<<nW4 / 256, 256>>>((const float4*)W, (uint2*)wh, nW4);
    vtrans_kernel<<<dim3(LK / 32, DM / 32, BATCH), 256>>>(v, vth);

    // 1) kt = tanh(K @ W^T) -> fp16. M=Lk, N=Dq, K=Dk. W broadcast.
    gemm_h<1><<<dim3(DM / BN, LK / BM, BATCH), NTH, DYN_SMEM>>>(
        kh, wh, nullptr, kth,
        LK, DM, DM, (long)LK * DM, 0L, (long)LK * DM);

    // 2) scores = Q @ kt^T -> att (fp32). M=Lq, N=Lk, K=Dq.
    gemm_h<0><<<dim3(LK / BN, LQ / BM, BATCH), NTH, DYN_SMEM>>>(
        qh, kth, att, nullptr,
        LQ, LK, DM, (long)LQ * DM, (long)LK * DM, (long)LQ * LK);

    // 3) softmax in place + emit fp16 att
    softmax_kernel<<<BATCH * LQ, 256>>>(att, kli, ath);

    // 4) out = att @ V. M=Lq, N=Dv, K=Lk.
    gemm_h<0><<<dim3(DM / BN, LQ / BM, BATCH), NTH, DYN_SMEM>>>(
        ath, vth, out, nullptr,
        LQ, DM, LK, (long)LQ * LK, (long)DM * LK, (long)LQ * DM);
}

// round 15
// speedup vs baseline: 1.2540x; 1.0731x over previous
#include <cuda_runtime.h>
#include <cuda_fp16.h>
#include <math.h>
#include <stdint.h>

// Problem shape (fixed): B=16, Lq=Lk=2048, Dq=Dk=Dv=1024
#define BATCH 16
#define LQ 2048
#define LK 2048
#define DM 1024

// GEMM tiling: CTA 128x128x64, warp 32x64, 8 warps, 3-stage cp.async, occ 2
#define BM 128
#define BN 128
#define BK 64
#define NTH 256

// smem: K-major fp16 tiles, 128B data rows padded to 144B (conflict-free LDSM:
// row stride 36 words -> 8-row groups cover banks 4*lr, all 32 banks once)
#define ROWB 144
#define TILE_B (128 * ROWB)          // 18432
#define STAGE_SZ (2 * TILE_B)        // 36864 (A + B)
#define NSTAGE 3
#define DYN_SMEM (NSTAGE * STAGE_SZ) // 110592 -> 2 CTAs/SM

// ---------------- device scratch (preconverted fp16 operands) ----------------
__device__ __half g_qh[(size_t)BATCH * LQ * DM];    // Q fp16
__device__ __half g_kh[(size_t)BATCH * LK * DM];    // K fp16
__device__ __half g_wh[(size_t)DM * DM];            // W fp16
__device__ __half g_kth[(size_t)BATCH * LK * DM];   // tanh(K W^T) fp16
__device__ __half g_vth[(size_t)BATCH * DM * LK];   // V^T fp16
__device__ __half g_ath[(size_t)BATCH * LQ * LK];   // att fp16

// ---------------- helpers ----------------
__device__ __forceinline__ uint2 round4h(float4 v) {
    __half2 H01; H01.x = __float2half(v.x); H01.y = __float2half(v.y);
    __half2 H23; H23.x = __float2half(v.z); H23.y = __float2half(v.w);
    uint2 r;
    r.x = *reinterpret_cast<uint32_t*>(&H01);
    r.y = *reinterpret_cast<uint32_t*>(&H23);
    return r;
}

__device__ __forceinline__ void mma_f16(float* d, const uint32_t* a, const uint32_t* b) {
    asm volatile(
        "mma.sync.aligned.m16n8k16.row.col.f32.f16.f16.f32 "
        "{%0,%1,%2,%3},{%4,%5,%6,%7},{%8,%9},{%0,%1,%2,%3};"
        : "+f"(d[0]), "+f"(d[1]), "+f"(d[2]), "+f"(d[3])
        : "r"(a[0]), "r"(a[1]), "r"(a[2]), "r"(a[3]), "r"(b[0]), "r"(b[1]));
}

__device__ __forceinline__ void ldsm4(uint32_t* r, uint32_t a) {
    asm volatile("ldmatrix.sync.aligned.m8n8.x4.shared.b16 {%0,%1,%2,%3}, [%4];"
                 : "=r"(r[0]), "=r"(r[1]), "=r"(r[2]), "=r"(r[3]) : "r"(a));
}

__device__ __forceinline__ void cpasync16(uint32_t dst, const void* src) {
    asm volatile("cp.async.cg.shared.global [%0], [%1], 16;" :: "r"(dst), "l"(src));
}
__device__ __forceinline__ void cp_commit() {
    asm volatile("cp.async.commit_group;" ::: "memory");
}
__device__ __forceinline__ void cp_wait1() {
    asm volatile("cp.async.wait_group 1;" ::: "memory");
}

// ------------- GEMM: C[M,N] = A[M,K] * B[N,K]^T, 1-term fp16 HMMA -------------
// EPI=0: fp32 out.  EPI=1: tanh -> fp16 out.
template <int EPI>
__global__ __launch_bounds__(NTH, 2)
void gemm_h(const __half* __restrict__ Ah, const __half* __restrict__ Bh,
            float* __restrict__ Cf, __half* __restrict__ Ch,
            int M, int N, int K, long sA, long sB, long sC)
{
    constexpr uint32_t A_T = 0;
    constexpr uint32_t B_T = TILE_B;

    extern __shared__ char sm[];
    const uint32_t usm = (uint32_t)__cvta_generic_to_shared(sm);

    const int tid = threadIdx.x;
    const int wid = tid >> 5;
    const int lane = tid & 31;
    const int g = lane >> 2;
    const int q = lane & 3;
    const int warpM = (wid & 3) * 32;    // 0,32,64,96
    const int warpN = (wid >> 2) * 64;   // 0,64

    const int bz = blockIdx.z;
    Ah += (long)bz * sA;
    Bh += (long)bz * sB;
    if (EPI == 0) Cf += (long)bz * sC; else Ch += (long)bz * sC;

    const int rowBlk = blockIdx.y * BM;
    const int colBlk = blockIdx.x * BN;

    float acc[2][8][4];
#pragma unroll
    for (int mt = 0; mt < 2; mt++)
#pragma unroll
        for (int nt = 0; nt < 8; nt++)
#pragma unroll
            for (int j = 0; j < 4; j++) acc[mt][nt][j] = 0.0f;

    // ldmatrix lane addressing
    const int jj = lane >> 3, lr = lane & 7;
    const uint32_t aOff = (uint32_t)((warpM + (jj & 1) * 8 + lr) * ROWB + (jj >> 1) * 16);
    const uint32_t bOff = (uint32_t)((warpN + (jj >> 1) * 8 + lr) * ROWB + (jj & 1) * 16);

    const int S = K / BK;

    // loader: 8 cp.async per thread (A 1024 + B 1024 chunks of 16B)
    auto load_stage = [&](int s, uint32_t bufo) {
        const int k0 = s * BK;
#pragma unroll
        for (int i = 0; i < 8; i++) {
            const int comp = i >> 2;               // 0=A, 1=B
            const int w = tid + (i & 3) * NTH;     // 0..1023
            const int r = w >> 3, ch = w & 7;
            const uint32_t dst = usm + bufo + comp * TILE_B + r * ROWB + ch * 16;
            const __half* src = comp ? Bh : Ah;
            const long row = (comp ? colBlk : rowBlk) + r;
            cpasync16(dst, src + row * (long)K + k0 + ch * 8);
        }
    };

    // prologue: stages 0,1 (2 groups in flight)
    load_stage(0, 0);        cp_commit();
    load_stage(1, STAGE_SZ); cp_commit();

    for (int s = 0; s < S; s++) {
        cp_wait1();          // stage s complete (exactly <=1 younger group)
        __syncthreads();

        if (s + 2 < S) load_stage(s + 2, (uint32_t)(((s + 2) % NSTAGE) * STAGE_SZ));
        cp_commit();         // uniform commit keeps wait arithmetic exact

        const uint32_t bufo = usm + (uint32_t)((s % NSTAGE) * STAGE_SZ);
#pragma unroll
        for (int kk = 0; kk < 4; kk++) {
            const uint32_t kb = bufo + kk * 32;
            uint32_t ah[2][4];
            ldsm4(ah[0], kb + A_T + aOff);
            ldsm4(ah[1], kb + A_T + aOff + 16 * ROWB);
#pragma unroll
            for (int half = 0; half < 2; half++) {
                uint32_t bh[8];
                ldsm4(bh + 0, kb + B_T + bOff + (half * 2 + 0) * 16 * ROWB);
                ldsm4(bh + 4, kb + B_T + bOff + (half * 2 + 1) * 16 * ROWB);
#pragma unroll
                for (int n2 = 0; n2 < 4; n2++) {
                    const int nt = half * 4 + n2;
#pragma unroll
                    for (int mt = 0; mt < 2; mt++)
                        mma_f16(acc[mt][nt], ah[mt], bh + n2 * 2);
                }
            }
        }
    }

    // ---- epilogue ----
#pragma unroll
    for (int mt = 0; mt < 2; mt++) {
        const long r0 = rowBlk + warpM + mt * 16 + g;
#pragma unroll
        for (int nt = 0; nt < 8; nt++) {
            const long c = colBlk + warpN + nt * 8 + q * 2;
            float d0 = acc[mt][nt][0], d1 = acc[mt][nt][1];
            float d2 = acc[mt][nt][2], d3 = acc[mt][nt][3];
            if (EPI == 1) {
                d0 = tanhf(d0); d1 = tanhf(d1); d2 = tanhf(d2); d3 = tanhf(d3);
                __half2 H0; H0.x = __float2half(d0); H0.y = __float2half(d1);
                __half2 H2; H2.x = __float2half(d2); H2.y = __float2half(d3);
                *reinterpret_cast<uint32_t*>(Ch + r0 * N + c)       = *reinterpret_cast<uint32_t*>(&H0);
                *reinterpret_cast<uint32_t*>(Ch + (r0 + 8) * N + c) = *reinterpret_cast<uint32_t*>(&H2);
            } else {
                float2 u; u.x = d0; u.y = d1;
                float2 w; w.x = d2; w.y = d3;
                *reinterpret_cast<float2*>(Cf + r0 * N + c) = u;
                *reinterpret_cast<float2*>(Cf + (r0 + 8) * N + c) = w;
            }
        }
    }
}

// ---------------- elementwise fp32 -> fp16 ----------------
__global__ __launch_bounds__(256) void conv_round_h(
    const float4* __restrict__ x, uint2* __restrict__ h, int n4)
{
    int i = blockIdx.x * blockDim.x + threadIdx.x;
    if (i < n4) h[i] = round4h(x[i]);
}

// ---------------- V transpose + fp16 round (vectorized 8B stores) ----------------
__global__ __launch_bounds__(256) void vtrans_kernel(
    const float* __restrict__ V, __half* __restrict__ Vh)
{
    __shared__ float t[32][33];   // t[k_local][n_local]
    const int b = blockIdx.z;
    const float* Vb = V + (long)b * LK * DM;
    const int k0 = blockIdx.x * 32, n0 = blockIdx.y * 32;
    const int tx = threadIdx.x & 31, ty = threadIdx.x >> 5;
#pragma unroll
    for (int i = 0; i < 4; i++)
        t[ty + i * 8][tx] = Vb[(long)(k0 + ty + i * 8) * DM + n0 + tx];
    __syncthreads();
    const int n_l = threadIdx.x >> 3;          // 0..31
    const int k4  = (threadIdx.x & 7) * 4;     // 0,4,...,28
    float4 v4;
    v4.x = t[k4 + 0][n_l];
    v4.y = t[k4 + 1][n_l];
    v4.z = t[k4 + 2][n_l];
    v4.w = t[k4 + 3][n_l];
    uint2 hv = round4h(v4);
    const long obase = (long)b * DM * LK;
    *reinterpret_cast<uint2*>(Vh + obase + (long)(n0 + n_l) * LK + k0 + k4) = hv;
}

// ---------------- softmax: fp32 att out + fp16 att out ----------------
__global__ __launch_bounds__(256) void softmax_kernel(
    float* __restrict__ att, const int* __restrict__ kli,
    __half* __restrict__ ath)
{
    const int row = blockIdx.x;
    const int b = row >> 11;
    float* p = att + (long)row * LK;
    const int* m = kli + (long)b * LK;
    const int tid = threadIdx.x;
    const int c0 = tid * 8;
    const float scale = 0.03125f;

    float vals[8];
    {
        float4 x0 = *reinterpret_cast<const float4*>(p + c0);
        float4 x1 = *reinterpret_cast<const float4*>(p + c0 + 4);
        int4 m0 = *reinterpret_cast<const int4*>(m + c0);
        int4 m1 = *reinterpret_cast<const int4*>(m + c0 + 4);
        vals[0] = (m0.x == 0) ? -1.0e9f : x0.x * scale;
        vals[1] = (m0.y == 0) ? -1.0e9f : x0.y * scale;
        vals[2] = (m0.z == 0) ? -1.0e9f : x0.z * scale;
        vals[3] = (m0.w == 0) ? -1.0e9f : x0.w * scale;
        vals[4] = (m1.x == 0) ? -1.0e9f : x1.x * scale;
        vals[5] = (m1.y == 0) ? -1.0e9f : x1.y * scale;
        vals[6] = (m1.z == 0) ? -1.0e9f : x1.z * scale;
        vals[7] = (m1.w == 0) ? -1.0e9f : x1.w * scale;
    }

    float mx = vals[0];
#pragma unroll
    for (int i = 1; i < 8; i++) mx = fmaxf(mx, vals[i]);

    __shared__ float red[8];
#pragma unroll
    for (int o = 16; o > 0; o >>= 1)
        mx = fmaxf(mx, __shfl_xor_sync(0xffffffffu, mx, o));
    if ((tid & 31) == 0) red[tid >> 5] = mx;
    __syncthreads();
    mx = red[0];
#pragma unroll
    for (int i = 1; i < 8; i++) mx = fmaxf(mx, red[i]);
    __syncthreads();

    float sum = 0.0f;
#pragma unroll
    for (int i = 0; i < 8; i++) {
        vals[i] = expf(vals[i] - mx);
        sum += vals[i];
    }
#pragma unroll
    for (int o = 16; o > 0; o >>= 1)
        sum += __shfl_xor_sync(0xffffffffu, sum, o);
    if ((tid & 31) == 0) red[tid >> 5] = sum;
    __syncthreads();
    sum = 0.0f;
#pragma unroll
    for (int i = 0; i < 8; i++) sum += red[i];

    const float inv = 1.0f / sum;
#pragma unroll
    for (int i = 0; i < 8; i++) vals[i] *= inv;

    float4 y0; y0.x = vals[0]; y0.y = vals[1]; y0.z = vals[2]; y0.w = vals[3];
    float4 y1; y1.x = vals[4]; y1.y = vals[5]; y1.z = vals[6]; y1.w = vals[7];
    *reinterpret_cast<float4*>(p + c0) = y0;
    *reinterpret_cast<float4*>(p + c0 + 4) = y1;

    uint2 h0 = round4h(y0);
    uint2 h1 = round4h(y1);
    uint4 H; H.x = h0.x; H.y = h0.y; H.z = h1.x; H.w = h1.y;
    *reinterpret_cast<uint4*>(ath + (long)row * LK + c0) = H;
}

// ---------------- launch ----------------
extern "C" void kernel_launch(void* const* d_in, const int* in_sizes, int n_in,
                              void* d_out, int out_size)
{
    const float* q   = (const float*)d_in[0];   // [B, Lq, Dq]
    const float* k   = (const float*)d_in[1];   // [B, Lk, Dk]
    const float* v   = (const float*)d_in[2];   // [B, Lk, Dv]
    const int*   kli = (const int*)  d_in[3];   // [B, Lk]
    const float* W   = (const float*)d_in[4];   // [Dq, Dk]

    float* out = (float*)d_out;                            // [B, Lq, Dv]
    float* att = out + (size_t)BATCH * LQ * DM;            // [B, Lq, Lk]

    __half *qh, *kh, *wh, *kth, *vth, *ath;
    cudaGetSymbolAddress((void**)&qh, g_qh);
    cudaGetSymbolAddress((void**)&kh, g_kh);
    cudaGetSymbolAddress((void**)&wh, g_wh);
    cudaGetSymbolAddress((void**)&kth, g_kth);
    cudaGetSymbolAddress((void**)&vth, g_vth);
    cudaGetSymbolAddress((void**)&ath, g_ath);

    cudaFuncSetAttribute(gemm_h<0>, cudaFuncAttributeMaxDynamicSharedMemorySize, DYN_SMEM);
    cudaFuncSetAttribute(gemm_h<1>, cudaFuncAttributeMaxDynamicSharedMemorySize, DYN_SMEM);

    // 0) preconvert operands
    const int nQK4 = BATCH * LQ * DM / 4;
    conv_round_h<<<nQK4 / 256, 256>>>((const float4*)q, (uint2*)qh, nQK4);
    conv_round_h<<<nQK4 / 256, 256>>>((const float4*)k, (uint2*)kh, nQK4);
    const int nW4 = DM * DM / 4;
    conv_round_h<<<nW4 / 256, 256>>>((const float4*)W, (uint2*)wh, nW4);
    vtrans_kernel<<<dim3(LK / 32, DM / 32, BATCH), 256>>>(v, vth);

    // 1) kt = tanh(K @ W^T) -> fp16. M=Lk, N=Dq, K=Dk. W broadcast.
    gemm_h<1><<<dim3(DM / BN, LK / BM, BATCH), NTH, DYN_SMEM>>>(
        kh, wh, nullptr, kth,
        LK, DM, DM, (long)LK * DM, 0L, (long)LK * DM);

    // 2) scores = Q @ kt^T -> att (fp32). M=Lq, N=Lk, K=Dq.
    gemm_h<0><<<dim3(LK / BN, LQ / BM, BATCH), NTH, DYN_SMEM>>>(
        qh, kth, att, nullptr,
        LQ, LK, DM, (long)LQ * DM, (long)LK * DM, (long)LQ * LK);

    // 3) softmax in place + emit fp16 att
    softmax_kernel<<<BATCH * LQ, 256>>>(att, kli, ath);

    // 4) out = att @ V. M=Lq, N=Dv, K=Lk.
    gemm_h<0><<<dim3(DM / BN, LQ / BM, BATCH), NTH, DYN_SMEM>>>(
        ath, vth, out, nullptr,
        LQ, DM, LK, (long)LQ * LK, (long)DM * LK, (long)LQ * DM);
}

// round 16
// speedup vs baseline: 1.2645x; 1.0084x over previous
#include <cuda_runtime.h>
#include <cuda_fp16.h>
#include <math.h>
#include <stdint.h>

// Problem shape (fixed): B=16, Lq=Lk=2048, Dq=Dk=Dv=1024
#define BATCH 16
#define LQ 2048
#define LK 2048
#define DM 1024

// GEMM tiling: CTA 128x128x64, warp 32x64, 8 warps, 3-stage cp.async, occ 2
#define BM 128
#define BN 128
#define BK 64
#define NTH 256

// smem: K-major fp16 tiles, 128B data rows padded to 144B (conflict-free LDSM)
#define ROWB 144
#define TILE_B (128 * ROWB)          // 18432
#define STAGE_SZ (2 * TILE_B)        // 36864 (A + B)
#define NSTAGE 3
#define DYN_SMEM (NSTAGE * STAGE_SZ) // 110592 -> 2 CTAs/SM

// ---------------- device scratch (preconverted fp16 operands) ----------------
__device__ __half g_qh[(size_t)BATCH * LQ * DM];    // Q fp16
__device__ __half g_kh[(size_t)BATCH * LK * DM];    // K fp16
__device__ __half g_wh[(size_t)DM * DM];            // W fp16
__device__ __half g_kth[(size_t)BATCH * LK * DM];   // tanh(K W^T) fp16
__device__ __half g_vth[(size_t)BATCH * DM * LK];   // V^T fp16
__device__ __half g_ath[(size_t)BATCH * LQ * LK];   // scaled scores fp16, then att fp16

// ---------------- helpers ----------------
__device__ __forceinline__ uint2 round4h(float4 v) {
    __half2 H01; H01.x = __float2half(v.x); H01.y = __float2half(v.y);
    __half2 H23; H23.x = __float2half(v.z); H23.y = __float2half(v.w);
    uint2 r;
    r.x = *reinterpret_cast<uint32_t*>(&H01);
    r.y = *reinterpret_cast<uint32_t*>(&H23);
    return r;
}

__device__ __forceinline__ void mma_f16(float* d, const uint32_t* a, const uint32_t* b) {
    asm volatile(
        "mma.sync.aligned.m16n8k16.row.col.f32.f16.f16.f32 "
        "{%0,%1,%2,%3},{%4,%5,%6,%7},{%8,%9},{%0,%1,%2,%3};"
        : "+f"(d[0]), "+f"(d[1]), "+f"(d[2]), "+f"(d[3])
        : "r"(a[0]), "r"(a[1]), "r"(a[2]), "r"(a[3]), "r"(b[0]), "r"(b[1]));
}

__device__ __forceinline__ void ldsm4(uint32_t* r, uint32_t a) {
    asm volatile("ldmatrix.sync.aligned.m8n8.x4.shared.b16 {%0,%1,%2,%3}, [%4];"
                 : "=r"(r[0]), "=r"(r[1]), "=r"(r[2]), "=r"(r[3]) : "r"(a));
}

__device__ __forceinline__ void cpasync16(uint32_t dst, const void* src) {
    asm volatile("cp.async.cg.shared.global [%0], [%1], 16;" :: "r"(dst), "l"(src));
}
__device__ __forceinline__ void cp_commit() {
    asm volatile("cp.async.commit_group;" ::: "memory");
}
__device__ __forceinline__ void cp_wait1() {
    asm volatile("cp.async.wait_group 1;" ::: "memory");
}

// ------------- GEMM: C[M,N] = A[M,K] * B[N,K]^T, 1-term fp16 HMMA -------------
// EPI=0: fp32 out.  EPI=1: tanh -> fp16 out.  EPI=2: *1/32 -> fp16 out.
template <int EPI>
__global__ __launch_bounds__(NTH, 2)
void gemm_h(const __half* __restrict__ Ah, const __half* __restrict__ Bh,
            float* __restrict__ Cf, __half* __restrict__ Ch,
            int M, int N, int K, long sA, long sB, long sC)
{
    constexpr uint32_t A_T = 0;
    constexpr uint32_t B_T = TILE_B;

    extern __shared__ char sm[];
    const uint32_t usm = (uint32_t)__cvta_generic_to_shared(sm);

    const int tid = threadIdx.x;
    const int wid = tid >> 5;
    const int lane = tid & 31;
    const int g = lane >> 2;
    const int q = lane & 3;
    const int warpM = (wid & 3) * 32;    // 0,32,64,96
    const int warpN = (wid >> 2) * 64;   // 0,64

    const int bz = blockIdx.z;
    Ah += (long)bz * sA;
    Bh += (long)bz * sB;
    if (EPI == 0) Cf += (long)bz * sC; else Ch += (long)bz * sC;

    const int rowBlk = blockIdx.y * BM;
    const int colBlk = blockIdx.x * BN;

    float acc[2][8][4];
#pragma unroll
    for (int mt = 0; mt < 2; mt++)
#pragma unroll
        for (int nt = 0; nt < 8; nt++)
#pragma unroll
            for (int j = 0; j < 4; j++) acc[mt][nt][j] = 0.0f;

    // ldmatrix lane addressing
    const int jj = lane >> 3, lr = lane & 7;
    const uint32_t aOff = (uint32_t)((warpM + (jj & 1) * 8 + lr) * ROWB + (jj >> 1) * 16);
    const uint32_t bOff = (uint32_t)((warpN + (jj >> 1) * 8 + lr) * ROWB + (jj & 1) * 16);

    const int S = K / BK;

    // loader: 8 cp.async per thread (A 1024 + B 1024 chunks of 16B)
    auto load_stage = [&](int s, uint32_t bufo) {
        const int k0 = s * BK;
#pragma unroll
        for (int i = 0; i < 8; i++) {
            const int comp = i >> 2;               // 0=A, 1=B
            const int w = tid + (i & 3) * NTH;     // 0..1023
            const int r = w >> 3, ch = w & 7;
            const uint32_t dst = usm + bufo + comp * TILE_B + r * ROWB + ch * 16;
            const __half* src = comp ? Bh : Ah;
            const long row = (comp ? colBlk : rowBlk) + r;
            cpasync16(dst, src + row * (long)K + k0 + ch * 8);
        }
    };

    // prologue: stages 0,1 (2 groups in flight)
    load_stage(0, 0);        cp_commit();
    load_stage(1, STAGE_SZ); cp_commit();

    for (int s = 0; s < S; s++) {
        cp_wait1();          // stage s complete
        __syncthreads();

        if (s + 2 < S) load_stage(s + 2, (uint32_t)(((s + 2) % NSTAGE) * STAGE_SZ));
        cp_commit();         // uniform commit keeps wait arithmetic exact

        const uint32_t bufo = usm + (uint32_t)((s % NSTAGE) * STAGE_SZ);
#pragma unroll
        for (int kk = 0; kk < 4; kk++) {
            const uint32_t kb = bufo + kk * 32;
            uint32_t ah[2][4];
            ldsm4(ah[0], kb + A_T + aOff);
            ldsm4(ah[1], kb + A_T + aOff + 16 * ROWB);
#pragma unroll
            for (int half = 0; half < 2; half++) {
                uint32_t bh[8];
                ldsm4(bh + 0, kb + B_T + bOff + (half * 2 + 0) * 16 * ROWB);
                ldsm4(bh + 4, kb + B_T + bOff + (half * 2 + 1) * 16 * ROWB);
#pragma unroll
                for (int n2 = 0; n2 < 4; n2++) {
                    const int nt = half * 4 + n2;
#pragma unroll
                    for (int mt = 0; mt < 2; mt++)
                        mma_f16(acc[mt][nt], ah[mt], bh + n2 * 2);
                }
            }
        }
    }

    // ---- epilogue ----
#pragma unroll
    for (int mt = 0; mt < 2; mt++) {
        const long r0 = rowBlk + warpM + mt * 16 + g;
#pragma unroll
        for (int nt = 0; nt < 8; nt++) {
            const long c = colBlk + warpN + nt * 8 + q * 2;
            float d0 = acc[mt][nt][0], d1 = acc[mt][nt][1];
            float d2 = acc[mt][nt][2], d3 = acc[mt][nt][3];
            if (EPI == 1 || EPI == 2) {
                if (EPI == 1) {
                    d0 = tanhf(d0); d1 = tanhf(d1); d2 = tanhf(d2); d3 = tanhf(d3);
                } else {
                    d0 *= 0.03125f; d1 *= 0.03125f; d2 *= 0.03125f; d3 *= 0.03125f;
                }
                __half2 H0; H0.x = __float2half(d0); H0.y = __float2half(d1);
                __half2 H2; H2.x = __float2half(d2); H2.y = __float2half(d3);
                *reinterpret_cast<uint32_t*>(Ch + r0 * N + c)       = *reinterpret_cast<uint32_t*>(&H0);
                *reinterpret_cast<uint32_t*>(Ch + (r0 + 8) * N + c) = *reinterpret_cast<uint32_t*>(&H2);
            } else {
                float2 u; u.x = d0; u.y = d1;
                float2 w; w.x = d2; w.y = d3;
                *reinterpret_cast<float2*>(Cf + r0 * N + c) = u;
                *reinterpret_cast<float2*>(Cf + (r0 + 8) * N + c) = w;
            }
        }
    }
}

// ---------------- fused Q+K fp32 -> fp16 ----------------
__global__ __launch_bounds__(256) void conv_qk_h(
    const float4* __restrict__ xq, uint2* __restrict__ hq,
    const float4* __restrict__ xk, uint2* __restrict__ hk, int n4)
{
    int i = blockIdx.x * blockDim.x + threadIdx.x;
    if (i < n4)            hq[i] = round4h(xq[i]);
    else if (i < 2 * n4)   hk[i - n4] = round4h(xk[i - n4]);
}

// ---------------- elementwise fp32 -> fp16 ----------------
__global__ __launch_bounds__(256) void conv_round_h(
    const float4* __restrict__ x, uint2* __restrict__ h, int n4)
{
    int i = blockIdx.x * blockDim.x + threadIdx.x;
    if (i < n4) h[i] = round4h(x[i]);
}

// ---------------- V transpose + fp16 round (vectorized 8B stores) ----------------
__global__ __launch_bounds__(256) void vtrans_kernel(
    const float* __restrict__ V, __half* __restrict__ Vh)
{
    __shared__ float t[32][33];   // t[k_local][n_local]
    const int b = blockIdx.z;
    const float* Vb = V + (long)b * LK * DM;
    const int k0 = blockIdx.x * 32, n0 = blockIdx.y * 32;
    const int tx = threadIdx.x & 31, ty = threadIdx.x >> 5;
#pragma unroll
    for (int i = 0; i < 4; i++)
        t[ty + i * 8][tx] = Vb[(long)(k0 + ty + i * 8) * DM + n0 + tx];
    __syncthreads();
    const int n_l = threadIdx.x >> 3;          // 0..31
    const int k4  = (threadIdx.x & 7) * 4;     // 0,4,...,28
    float4 v4;
    v4.x = t[k4 + 0][n_l];
    v4.y = t[k4 + 1][n_l];
    v4.z = t[k4 + 2][n_l];
    v4.w = t[k4 + 3][n_l];
    uint2 hv = round4h(v4);
    const long obase = (long)b * DM * LK;
    *reinterpret_cast<uint2*>(Vh + obase + (long)(n0 + n_l) * LK + k0 + k4) = hv;
}

// ---------------- softmax: fp16 scaled scores in -> fp32 att + fp16 att ----------------
__global__ __launch_bounds__(256) void softmax_kernel(
    __half* __restrict__ sc,            // in: scaled scores fp16; out: att fp16 (in place)
    const int* __restrict__ kli,
    float* __restrict__ att)            // out: att fp32
{
    const int row = blockIdx.x;
    const int b = row >> 11;
    __half* ps = sc + (long)row * LK;
    float* p = att + (long)row * LK;
    const int* m = kli + (long)b * LK;
    const int tid = threadIdx.x;
    const int c0 = tid * 8;

    float vals[8];
    {
        uint4 X = *reinterpret_cast<const uint4*>(ps + c0);
        int4 m0 = *reinterpret_cast<const int4*>(m + c0);
        int4 m1 = *reinterpret_cast<const int4*>(m + c0 + 4);
        __half2 h0 = *reinterpret_cast<__half2*>(&X.x);
        __half2 h1 = *reinterpret_cast<__half2*>(&X.y);
        __half2 h2 = *reinterpret_cast<__half2*>(&X.z);
        __half2 h3 = *reinterpret_cast<__half2*>(&X.w);
        vals[0] = (m0.x == 0) ? -1.0e9f : __half2float(h0.x);
        vals[1] = (m0.y == 0) ? -1.0e9f : __half2float(h0.y);
        vals[2] = (m0.z == 0) ? -1.0e9f : __half2float(h1.x);
        vals[3] = (m0.w == 0) ? -1.0e9f : __half2float(h1.y);
        vals[4] = (m1.x == 0) ? -1.0e9f : __half2float(h2.x);
        vals[5] = (m1.y == 0) ? -1.0e9f : __half2float(h2.y);
        vals[6] = (m1.z == 0) ? -1.0e9f : __half2float(h3.x);
        vals[7] = (m1.w == 0) ? -1.0e9f : __half2float(h3.y);
    }

    float mx = vals[0];
#pragma unroll
    for (int i = 1; i < 8; i++) mx = fmaxf(mx, vals[i]);

    __shared__ float red[8];
#pragma unroll
    for (int o = 16; o > 0; o >>= 1)
        mx = fmaxf(mx, __shfl_xor_sync(0xffffffffu, mx, o));
    if ((tid & 31) == 0) red[tid >> 5] = mx;
    __syncthreads();
    mx = red[0];
#pragma unroll
    for (int i = 1; i < 8; i++) mx = fmaxf(mx, red[i]);
    __syncthreads();

    float sum = 0.0f;
#pragma unroll
    for (int i = 0; i < 8; i++) {
        vals[i] = expf(vals[i] - mx);
        sum += vals[i];
    }
#pragma unroll
    for (int o = 16; o > 0; o >>= 1)
        sum += __shfl_xor_sync(0xffffffffu, sum, o);
    if ((tid & 31) == 0) red[tid >> 5] = sum;
    __syncthreads();
    sum = 0.0f;
#pragma unroll
    for (int i = 0; i < 8; i++) sum += red[i];

    const float inv = 1.0f / sum;
#pragma unroll
    for (int i = 0; i < 8; i++) vals[i] *= inv;

    float4 y0; y0.x = vals[0]; y0.y = vals[1]; y0.z = vals[2]; y0.w = vals[3];
    float4 y1; y1.x = vals[4]; y1.y = vals[5]; y1.z = vals[6]; y1.w = vals[7];
    *reinterpret_cast<float4*>(p + c0) = y0;
    *reinterpret_cast<float4*>(p + c0 + 4) = y1;

    uint2 h0 = round4h(y0);
    uint2 h1 = round4h(y1);
    uint4 H; H.x = h0.x; H.y = h0.y; H.z = h1.x; H.w = h1.y;
    *reinterpret_cast<uint4*>(ps + c0) = H;
}

// ---------------- launch ----------------
extern "C" void kernel_launch(void* const* d_in, const int* in_sizes, int n_in,
                              void* d_out, int out_size)
{
    const float* q   = (const float*)d_in[0];   // [B, Lq, Dq]
    const float* k   = (const float*)d_in[1];   // [B, Lk, Dk]
    const float* v   = (const float*)d_in[2];   // [B, Lk, Dv]
    const int*   kli = (const int*)  d_in[3];   // [B, Lk]
    const float* W   = (const float*)d_in[4];   // [Dq, Dk]

    float* out = (float*)d_out;                            // [B, Lq, Dv]
    float* att = out + (size_t)BATCH * LQ * DM;            // [B, Lq, Lk]

    __half *qh, *kh, *wh, *kth, *vth, *ath;
    cudaGetSymbolAddress((void**)&qh, g_qh);
    cudaGetSymbolAddress((void**)&kh, g_kh);
    cudaGetSymbolAddress((void**)&wh, g_wh);
    cudaGetSymbolAddress((void**)&kth, g_kth);
    cudaGetSymbolAddress((void**)&vth, g_vth);
    cudaGetSymbolAddress((void**)&ath, g_ath);

    cudaFuncSetAttribute(gemm_h<0>, cudaFuncAttributeMaxDynamicSharedMemorySize, DYN_SMEM);
    cudaFuncSetAttribute(gemm_h<1>, cudaFuncAttributeMaxDynamicSharedMemorySize, DYN_SMEM);
    cudaFuncSetAttribute(gemm_h<2>, cudaFuncAttributeMaxDynamicSharedMemorySize, DYN_SMEM);

    // 0) preconvert operands
    const int nQK4 = BATCH * LQ * DM / 4;
    conv_qk_h<<<2 * nQK4 / 256, 256>>>((const float4*)q, (uint2*)qh,
                                       (const float4*)k, (uint2*)kh, nQK4);
    const int nW4 = DM * DM / 4;
    conv_round_h<<<nW4 / 256, 256>>>((const float4*)W, (uint2*)wh, nW4);
    vtrans_kernel<<<dim3(LK / 32, DM / 32, BATCH), 256>>>(v, vth);

    // 1) kt = tanh(K @ W^T) -> fp16. M=Lk, N=Dq, K=Dk. W broadcast.
    gemm_h<1><<<dim3(DM / BN, LK / BM, BATCH), NTH, DYN_SMEM>>>(
        kh, wh, nullptr, kth,
        LK, DM, DM, (long)LK * DM, 0L, (long)LK * DM);

    // 2) scaled scores = (Q @ kt^T)/32 -> fp16 into ath. M=Lq, N=Lk, K=Dq.
    gemm_h<2><<<dim3(LK / BN, LQ / BM, BATCH), NTH, DYN_SMEM>>>(
        qh, kth, nullptr, ath,
        LQ, LK, DM, (long)LQ * DM, (long)LK * DM, (long)LQ * LK);

    // 3) softmax: fp16 scores -> fp32 att (d_out) + fp16 att (in place over ath)
    softmax_kernel<<<BATCH * LQ, 256>>>(ath, kli, att);

    // 4) out = att @ V. M=Lq, N=Dv, K=Lk.
    gemm_h<0><<<dim3(DM / BN, LQ / BM, BATCH), NTH, DYN_SMEM>>>(
        ath, vth, out, nullptr,
        LQ, DM, LK, (long)LQ * LK, (long)DM * LK, (long)LQ * DM);
}